// round 2
// baseline (speedup 1.0000x reference)
#include <cuda_runtime.h>
#include <cuda_bf16.h>
#include <float.h>
#include <math.h>

// Problem constants (fixed by setup_inputs: N=32768, D=768, task_id=9 -> 100 classes)
#define D       768
#define C       100
#define C2      200
#define NMAX    32768
#define INV_T   2.0f      // 1 / TEMPERATURE(0.5)
#define EPS_N   1e-12f

// ---- scratch (static __device__ globals; no allocation allowed) ----
__device__ int   g_counts[128];
__device__ int   g_offsets[132];
__device__ int   g_cursor[128];
__device__ int   g_nvalid;
__device__ int   g_perm[NMAX];
__device__ float g_sums[2 * C * D];     // [half][class][col]
__device__ float g_z[C2 * D];           // normalized prototypes, row-major
__device__ float g_zT[D * C2];          // normalized prototypes, transposed
__device__ float g_rowloss[C2];

// ---------------------------------------------------------------- zero
__global__ void k_zero() {
    int t = threadIdx.x;
    if (t < 128) { g_counts[t] = 0; g_cursor[t] = 0; }
}

// ---------------------------------------------------------------- histogram
__global__ void k_hist(const int* __restrict__ labels, int n) {
    __shared__ int h[C];
    int t = threadIdx.x;
    if (t < C) h[t] = 0;
    __syncthreads();
    for (int i = blockIdx.x * blockDim.x + t; i < n; i += gridDim.x * blockDim.x)
        atomicAdd(&h[labels[i]], 1);
    __syncthreads();
    if (t < C && h[t] > 0) atomicAdd(&g_counts[t], h[t]);
}

// ---------------------------------------------------------------- exclusive scan (tiny)
__global__ void k_scan() {
    if (threadIdx.x == 0) {
        int acc = 0, nv = 0;
        for (int c = 0; c < C; c++) {
            g_offsets[c] = acc;
            acc += g_counts[c];
            if (g_counts[c] > 0) nv += 2;
        }
        g_offsets[C] = acc;
        g_nvalid = nv;
    }
}

// ---------------------------------------------------------------- scatter into label-sorted perm
__global__ void k_scatter(const int* __restrict__ labels, int n) {
    __shared__ int h[C];
    __shared__ int base[C];
    int t = threadIdx.x;
    if (t < C) h[t] = 0;
    __syncthreads();
    int i = blockIdx.x * blockDim.x + t;
    int lab = 0, rank = 0;
    bool act = (i < n);
    if (act) { lab = labels[i]; rank = atomicAdd(&h[lab], 1); }
    __syncthreads();
    if (t < C && h[t] > 0) base[t] = atomicAdd(&g_cursor[t], h[t]);
    __syncthreads();
    if (act) g_perm[g_offsets[lab] + base[lab] + rank] = i;
}

// ---------------------------------------------------------------- main segment-sum (atomic-free)
// grid: (C, D/128), block: 128. Each block owns one (class, 128-col tile),
// serially accumulates all rows of that class. 8-deep unroll for MLP.
__global__ void k_segsum(const float* __restrict__ z1, const float* __restrict__ z2) {
    int c   = blockIdx.x;
    int col = blockIdx.y * 128 + threadIdx.x;
    int s = g_offsets[c];
    int e = g_offsets[c + 1];

    float a1 = 0.f, a2 = 0.f;
    int r = s;
    for (; r + 8 <= e; r += 8) {
        int idx[8];
#pragma unroll
        for (int u = 0; u < 8; u++) idx[u] = g_perm[r + u];
        float v1[8], v2[8];
#pragma unroll
        for (int u = 0; u < 8; u++) v1[u] = __ldg(&z1[(size_t)idx[u] * D + col]);
#pragma unroll
        for (int u = 0; u < 8; u++) v2[u] = __ldg(&z2[(size_t)idx[u] * D + col]);
#pragma unroll
        for (int u = 0; u < 8; u++) { a1 += v1[u]; a2 += v2[u]; }
    }
    for (; r < e; r++) {
        int i = g_perm[r];
        a1 += __ldg(&z1[(size_t)i * D + col]);
        a2 += __ldg(&z2[(size_t)i * D + col]);
    }
    g_sums[c * D + col]         = a1;
    g_sums[C * D + c * D + col] = a2;
}

// ---------------------------------------------------------------- prototypes + l2 normalize
// grid: C2 blocks (one per prototype row), block: 256.
__global__ void k_proto(float* __restrict__ out) {
    int row  = blockIdx.x;          // 0..199
    int c    = row % C;
    int half = row / C;
    int t    = threadIdx.x;

    float denom = fmaxf((float)g_counts[c], 1.0f);
    float inv_d = 1.0f / denom;

    float p[3];
#pragma unroll
    for (int k = 0; k < 3; k++) {
        int col = t + k * 256;
        p[k] = g_sums[half * (C * D) + c * D + col] * inv_d;
        // unnormalized prototype goes straight to output (+1 for loss scalar)
        out[1 + half * (C * D) + c * D + col] = p[k];
    }

    __shared__ float red[256];
    red[t] = p[0] * p[0] + p[1] * p[1] + p[2] * p[2];
    __syncthreads();
    for (int o = 128; o > 0; o >>= 1) {
        if (t < o) red[t] += red[t + o];
        __syncthreads();
    }
    float norm = sqrtf(red[0]);
    float inv  = 1.0f / fmaxf(norm, EPS_N);
#pragma unroll
    for (int k = 0; k < 3; k++) {
        int col = t + k * 256;
        float zn = p[k] * inv;
        g_z[row * D + col]    = zn;
        g_zT[col * C2 + row]  = zn;
    }
}

// ---------------------------------------------------------------- fused Gram-row + masked softmax
// grid: C2/2 = 100 blocks, each computes 2 full logit rows and their log-prob-at-pos.
__device__ __forceinline__ float red_max(float v, float* red) {
    int t = threadIdx.x;
    red[t] = v; __syncthreads();
    for (int o = 128; o > 0; o >>= 1) {
        if (t < o) red[t] = fmaxf(red[t], red[t + o]);
        __syncthreads();
    }
    float r = red[0]; __syncthreads();
    return r;
}
__device__ __forceinline__ float red_sum(float v, float* red) {
    int t = threadIdx.x;
    red[t] = v; __syncthreads();
    for (int o = 128; o > 0; o >>= 1) {
        if (t < o) red[t] += red[t + o];
        __syncthreads();
    }
    float r = red[0]; __syncthreads();
    return r;
}

__global__ void k_rowloss() {
    __shared__ float zi0[D];
    __shared__ float zi1[D];
    __shared__ float sl[256];
    __shared__ float red[256];

    int i0 = blockIdx.x * 2;
    int i1 = i0 + 1;
    int t  = threadIdx.x;

    for (int k = t; k < D; k += 256) {
        zi0[k] = g_z[i0 * D + k];
        zi1[k] = g_z[i1 * D + k];
    }
    __syncthreads();

    bool act = (t < C2);
    float d0 = 0.f, d1 = 0.f;
    if (act) {
#pragma unroll 4
        for (int k = 0; k < D; k++) {
            float v = g_zT[k * C2 + t];
            d0 = fmaf(zi0[k], v, d0);
            d1 = fmaf(zi1[k], v, d1);
        }
    }
    float l0 = d0 * INV_T;
    float l1 = d1 * INV_T;
    bool vt = act && (g_counts[t % C] > 0);

    // ---- row i0 ----
    {
        float m = red_max(vt ? l0 : -FLT_MAX, red);
        float e = (vt && t != i0) ? expf(l0 - m) : 0.0f;
        float S = red_sum(e, red);
        sl[t] = act ? l0 : 0.0f;
        __syncthreads();
        if (t == 0) {
            int pos = (i0 + C) % C2;
            bool vi = g_counts[i0 % C] > 0;
            bool vp = g_counts[pos % C] > 0;
            float lp = (sl[pos] - m) - logf(S);
            g_rowloss[i0] = (vi && vp) ? lp : 0.0f;
        }
        __syncthreads();
    }
    // ---- row i1 ----
    {
        float m = red_max(vt ? l1 : -FLT_MAX, red);
        float e = (vt && t != i1) ? expf(l1 - m) : 0.0f;
        float S = red_sum(e, red);
        sl[t] = act ? l1 : 0.0f;
        __syncthreads();
        if (t == 0) {
            int pos = (i1 + C) % C2;
            bool vi = g_counts[i1 % C] > 0;
            bool vp = g_counts[pos % C] > 0;
            float lp = (sl[pos] - m) - logf(S);
            g_rowloss[i1] = (vi && vp) ? lp : 0.0f;
        }
    }
}

// ---------------------------------------------------------------- final loss reduction (deterministic)
__global__ void k_final(float* __restrict__ out) {
    __shared__ float red[256];
    int t = threadIdx.x;
    float v = (t < C2) ? g_rowloss[t] : 0.0f;
    red[t] = v; __syncthreads();
    for (int o = 128; o > 0; o >>= 1) {
        if (t < o) red[t] += red[t + o];
        __syncthreads();
    }
    if (t == 0) out[0] = -red[0] / fmaxf((float)g_nvalid, 1.0f);
}

// ---------------------------------------------------------------- launch
extern "C" void kernel_launch(void* const* d_in, const int* in_sizes, int n_in,
                              void* d_out, int out_size) {
    const float* z1     = (const float*)d_in[0];
    const float* z2     = (const float*)d_in[1];
    const int*   labels = (const int*)d_in[2];
    float*       out    = (float*)d_out;
    int n = in_sizes[2];   // 32768

    int nb = (n + 255) / 256;

    k_zero<<<1, 128>>>();
    k_hist<<<nb, 256>>>(labels, n);
    k_scan<<<1, 32>>>();
    k_scatter<<<nb, 256>>>(labels, n);
    k_segsum<<<dim3(C, D / 128), 128>>>(z1, z2);
    k_proto<<<C2, 256>>>(out);
    k_rowloss<<<C2 / 2, 256>>>();
    k_final<<<1, 256>>>(out);
}

// round 4
// speedup vs baseline: 1.3465x; 1.3465x over previous
#include <cuda_runtime.h>
#include <cuda_bf16.h>
#include <float.h>
#include <math.h>

// Fixed by setup_inputs: N=32768, D=768, task_id=9 -> 100 classes
#define D       768
#define D4      192
#define C       100
#define C2      200
#define NMAX    32768
#define CHUNKS  8
#define INV_T   2.0f
#define EPS_N   1e-12f

// ---- static scratch (no allocation allowed) ----
__device__ int    g_counts[128];
__device__ int    g_offsets[104];
__device__ int    g_cursor[128];
__device__ int    g_done;
__device__ int    g_perm[NMAX];
__device__ float4 g_part1[C * CHUNKS * D4];   // per-(class,chunk) partial sums, z1
__device__ float4 g_part2[C * CHUNKS * D4];   // z2
__device__ float4 g_z4[C2 * D4];              // normalized prototypes, row-major
__device__ float  g_zT[D * C2];               // transposed
__device__ float  g_rowloss[C2];

// ---------------------------------------------------------------- init
__global__ void k_init() {
    int t = threadIdx.x;
    if (t < 128) { g_counts[t] = 0; g_cursor[t] = 0; }
    if (t == 0) g_done = 0;
}

// ---------------------------------------------------------------- histogram (int4 loads)
__global__ void k_hist(const int* __restrict__ labels, int n) {
    __shared__ int h[C];
    int t = threadIdx.x;
    if (t < C) h[t] = 0;
    __syncthreads();
    int n4 = n >> 2;
    const int4* l4 = (const int4*)labels;
    for (int i = blockIdx.x * blockDim.x + t; i < n4; i += gridDim.x * blockDim.x) {
        int4 v = l4[i];
        atomicAdd(&h[v.x], 1); atomicAdd(&h[v.y], 1);
        atomicAdd(&h[v.z], 1); atomicAdd(&h[v.w], 1);
    }
    if (blockIdx.x == 0 && t < (n & 3)) atomicAdd(&g_counts[labels[(n4 << 2) + t]], 1);
    __syncthreads();
    if (t < C && h[t]) atomicAdd(&g_counts[t], h[t]);
}

// ---------------------------------------------------------------- scatter (scan fused in-block)
__global__ void k_scatter(const int* __restrict__ labels, int n) {
    __shared__ int h[C], base[C], offs[C + 1];
    int t = threadIdx.x;                    // 256
    if (t < C) h[t] = 0;
    __syncthreads();
    if (t == 0) {
        int acc = 0;
        for (int c = 0; c < C; c++) { offs[c] = acc; acc += g_counts[c]; }
        offs[C] = acc;
    }
    __syncthreads();

    int i0 = (blockIdx.x * blockDim.x + t) * 4;
    int lab[4], rank[4];
    bool a[4];
    if (i0 + 3 < n) {
        int4 v = ((const int4*)labels)[blockIdx.x * blockDim.x + t];
        lab[0] = v.x; lab[1] = v.y; lab[2] = v.z; lab[3] = v.w;
#pragma unroll
        for (int u = 0; u < 4; u++) { a[u] = true; rank[u] = atomicAdd(&h[lab[u]], 1); }
    } else {
#pragma unroll
        for (int u = 0; u < 4; u++) {
            a[u] = (i0 + u) < n;
            if (a[u]) { lab[u] = labels[i0 + u]; rank[u] = atomicAdd(&h[lab[u]], 1); }
        }
    }
    __syncthreads();
    if (t < C && h[t]) base[t] = atomicAdd(&g_cursor[t], h[t]);
    __syncthreads();
#pragma unroll
    for (int u = 0; u < 4; u++)
        if (a[u]) g_perm[offs[lab[u]] + base[lab[u]] + rank[u]] = i0 + u;
    if (blockIdx.x == 0 && t <= C) g_offsets[t] = offs[t];
}

// ---------------------------------------------------------------- segment-sum, float4, chunked
// grid: (C, CHUNKS), block: 192. Each thread owns one float4 column group of the
// full 768-wide row; each block accumulates ~cnt/8 rows of one class.
__global__ void __launch_bounds__(192) k_segsum(const float* __restrict__ z1,
                                                const float* __restrict__ z2) {
    __shared__ int s_idx[256];
    int c = blockIdx.x, ch = blockIdx.y, t = threadIdx.x;
    int s = g_offsets[c], e = g_offsets[c + 1];
    int cnt = e - s;
    int per = (cnt + CHUNKS - 1) / CHUNKS;
    int r0 = s + ch * per;
    int r1 = min(r0 + per, e);

    const float4* z1v = (const float4*)z1;
    const float4* z2v = (const float4*)z2;
    float4 a1 = make_float4(0.f, 0.f, 0.f, 0.f);
    float4 a2 = make_float4(0.f, 0.f, 0.f, 0.f);

    for (int base = r0; base < r1; base += 256) {
        int m = min(256, r1 - base);
        __syncthreads();
        for (int j = t; j < m; j += 192) s_idx[j] = g_perm[base + j];
        __syncthreads();
        int j = 0;
        for (; j + 4 <= m; j += 4) {
            int p0 = s_idx[j], p1 = s_idx[j + 1], p2 = s_idx[j + 2], p3 = s_idx[j + 3];
            float4 u0 = z1v[p0 * D4 + t], u1 = z1v[p1 * D4 + t];
            float4 u2 = z1v[p2 * D4 + t], u3 = z1v[p3 * D4 + t];
            float4 w0 = z2v[p0 * D4 + t], w1 = z2v[p1 * D4 + t];
            float4 w2 = z2v[p2 * D4 + t], w3 = z2v[p3 * D4 + t];
            a1.x += (u0.x + u1.x) + (u2.x + u3.x);
            a1.y += (u0.y + u1.y) + (u2.y + u3.y);
            a1.z += (u0.z + u1.z) + (u2.z + u3.z);
            a1.w += (u0.w + u1.w) + (u2.w + u3.w);
            a2.x += (w0.x + w1.x) + (w2.x + w3.x);
            a2.y += (w0.y + w1.y) + (w2.y + w3.y);
            a2.z += (w0.z + w1.z) + (w2.z + w3.z);
            a2.w += (w0.w + w1.w) + (w2.w + w3.w);
        }
        for (; j < m; j++) {
            int p = s_idx[j];
            float4 u = z1v[p * D4 + t], w = z2v[p * D4 + t];
            a1.x += u.x; a1.y += u.y; a1.z += u.z; a1.w += u.w;
            a2.x += w.x; a2.y += w.y; a2.z += w.z; a2.w += w.w;
        }
    }
    int o = (c * CHUNKS + ch) * D4 + t;
    g_part1[o] = a1;
    g_part2[o] = a2;
}

// ---------------------------------------------------------------- prototypes + l2 normalize
// grid: C2 blocks, block: 192. Deterministic fixed-order chunk reduction.
__global__ void k_proto(float* __restrict__ out) {
    __shared__ float red[192];
    int row = blockIdx.x, t = threadIdx.x;
    int half = row / C, c = row - half * C;
    const float4* P = half ? g_part2 : g_part1;

    float4 p = make_float4(0.f, 0.f, 0.f, 0.f);
#pragma unroll
    for (int ch = 0; ch < CHUNKS; ch++) {
        float4 q = P[(c * CHUNKS + ch) * D4 + t];
        p.x += q.x; p.y += q.y; p.z += q.z; p.w += q.w;
    }
    float inv_d = 1.0f / fmaxf((float)g_counts[c], 1.0f);
    p.x *= inv_d; p.y *= inv_d; p.z *= inv_d; p.w *= inv_d;

    float* o = out + 1 + row * D + t * 4;   // out[0] = loss; unaligned by 4B -> scalar stores
    o[0] = p.x; o[1] = p.y; o[2] = p.z; o[3] = p.w;

    red[t] = p.x * p.x + p.y * p.y + p.z * p.z + p.w * p.w;
    __syncthreads();
    if (t < 64) red[t] += red[t + 64] + red[t + 128];
    __syncthreads();
    for (int o2 = 32; o2 > 0; o2 >>= 1) {
        if (t < o2) red[t] += red[t + o2];
        __syncthreads();
    }
    float inv = 1.0f / fmaxf(sqrtf(red[0]), EPS_N);
    float4 zn = make_float4(p.x * inv, p.y * inv, p.z * inv, p.w * inv);
    g_z4[row * D4 + t] = zn;
    int col = t * 4;
    g_zT[col * C2 + row]       = zn.x;
    g_zT[(col + 1) * C2 + row] = zn.y;
    g_zT[(col + 2) * C2 + row] = zn.z;
    g_zT[(col + 3) * C2 + row] = zn.w;
}

// ---------------------------------------------------------------- fused Gram + softmax + final
// grid: C2/4 = 50 blocks, 4 rows each; last block does the final loss reduction.
__global__ void __launch_bounds__(256) k_rowloss(float* __restrict__ out) {
    __shared__ float4 zi[4][D4];
    __shared__ float red[256], sl[256];
    __shared__ int isLast;
    int t = threadIdx.x;
    int ib = blockIdx.x * 4;

    for (int idx = t; idx < D4; idx += 256) {
#pragma unroll
        for (int q = 0; q < 4; q++) zi[q][idx] = g_z4[(ib + q) * D4 + idx];
    }
    __syncthreads();

    bool act = t < C2;
    int cv = act ? g_counts[t % C] : 0;
    float d0 = 0.f, d1 = 0.f, d2 = 0.f, d3 = 0.f;
    if (act) {
#pragma unroll 4
        for (int k4 = 0; k4 < D4; k4++) {
            float4 v0 = zi[0][k4], v1 = zi[1][k4], v2 = zi[2][k4], v3 = zi[3][k4];
            const float* zT = &g_zT[(k4 * 4) * C2 + t];
            float b0 = zT[0], b1 = zT[C2], b2 = zT[2 * C2], b3 = zT[3 * C2];
            d0 = fmaf(v0.x, b0, d0); d0 = fmaf(v0.y, b1, d0);
            d0 = fmaf(v0.z, b2, d0); d0 = fmaf(v0.w, b3, d0);
            d1 = fmaf(v1.x, b0, d1); d1 = fmaf(v1.y, b1, d1);
            d1 = fmaf(v1.z, b2, d1); d1 = fmaf(v1.w, b3, d1);
            d2 = fmaf(v2.x, b0, d2); d2 = fmaf(v2.y, b1, d2);
            d2 = fmaf(v2.z, b2, d2); d2 = fmaf(v2.w, b3, d2);
            d3 = fmaf(v3.x, b0, d3); d3 = fmaf(v3.y, b1, d3);
            d3 = fmaf(v3.z, b2, d3); d3 = fmaf(v3.w, b3, d3);
        }
    }
    float dq[4] = {d0, d1, d2, d3};
    bool vt = act && (cv > 0);

#pragma unroll
    for (int q = 0; q < 4; q++) {
        int i = ib + q;
        float l = dq[q] * INV_T;
        red[t] = vt ? l : -FLT_MAX;
        __syncthreads();
        for (int o2 = 128; o2 > 0; o2 >>= 1) {
            if (t < o2) red[t] = fmaxf(red[t], red[t + o2]);
            __syncthreads();
        }
        float m = red[0];
        __syncthreads();
        red[t] = (vt && t != i) ? expf(l - m) : 0.f;
        sl[t] = act ? l : 0.f;
        __syncthreads();
        for (int o2 = 128; o2 > 0; o2 >>= 1) {
            if (t < o2) red[t] += red[t + o2];
            __syncthreads();
        }
        float S = red[0];
        if (t == 0) {
            int pos = (i + C) % C2;
            bool vi = g_counts[i % C] > 0;   // pos%C == i%C -> same validity
            g_rowloss[i] = vi ? (sl[pos] - m - logf(S)) : 0.f;
        }
        __syncthreads();
    }

    if (t == 0) {
        __threadfence();
        isLast = (atomicAdd(&g_done, 1) == gridDim.x - 1);
    }
    __syncthreads();
    if (isLast) {
        red[t] = (t < C2) ? g_rowloss[t] : 0.f;
        __syncthreads();
        for (int o2 = 128; o2 > 0; o2 >>= 1) {
            if (t < o2) red[t] += red[t + o2];
            __syncthreads();
        }
        float tot = red[0];
        __syncthreads();
        red[t] = (t < C) ? (g_counts[t] > 0 ? 2.f : 0.f) : 0.f;
        __syncthreads();
        for (int o2 = 128; o2 > 0; o2 >>= 1) {
            if (t < o2) red[t] += red[t + o2];
            __syncthreads();
        }
        if (t == 0) out[0] = -tot / fmaxf(red[0], 1.f);
    }
}

// ---------------------------------------------------------------- launch
extern "C" void kernel_launch(void* const* d_in, const int* in_sizes, int n_in,
                              void* d_out, int out_size) {
    const float* z1     = (const float*)d_in[0];
    const float* z2     = (const float*)d_in[1];
    const int*   labels = (const int*)d_in[2];
    float*       out    = (float*)d_out;
    int n = in_sizes[2];   // 32768

    k_init<<<1, 256>>>();
    k_hist<<<32, 256>>>(labels, n);
    k_scatter<<<(n + 1023) / 1024, 256>>>(labels, n);
    k_segsum<<<dim3(C, CHUNKS), 192>>>(z1, z2);
    k_proto<<<C2, 192>>>(out);
    k_rowloss<<<C2 / 4, 256>>>(out);
}

// round 7
// speedup vs baseline: 1.3469x; 1.0003x over previous
#include <cuda_runtime.h>
#include <cuda_bf16.h>
#include <float.h>
#include <math.h>

// Fixed by setup_inputs: N=32768, D=768, task_id=9 -> 100 classes
#define D       768
#define D4      192
#define C       100
#define C2      200
#define NMAX    32768
#define CHUNKS  16
#define NB      296             // 2 blocks/SM x 148 SMs: co-residency guaranteed
#define NT      192
#define INV_T   2.0f
#define EPS_N   1e-12f

// ---- static scratch (no allocation allowed) ----
__device__ int    g_bar[8];               // per-phase arrive counters (zeroed by k_reset)
__device__ int    g_hist_part[NB][C];
__device__ int    g_counts[C];
__device__ int    g_offsets[C + 1];
__device__ int    g_perm[NMAX];
__device__ float4 g_part[2][C][CHUNKS][D4];
__device__ float4 g_z4[C2 * D4];
__device__ float  g_zT[D * C2];
__device__ float  g_rowloss[C2];

__global__ void k_reset() {
    if (threadIdx.x < 8) g_bar[threadIdx.x] = 0;
}

// monotone per-phase counting barrier; counters never reused within a launch
__device__ __forceinline__ void grid_barrier(int k) {
    __syncthreads();
    if (threadIdx.x == 0) {
        __threadfence();
        atomicAdd(&g_bar[k], 1);
        while (*((volatile int*)&g_bar[k]) < NB) __nanosleep(64);
        __threadfence();
    }
    __syncthreads();
}

__global__ void __launch_bounds__(NT, 2) k_mega(const float* __restrict__ z1,
                                                const float* __restrict__ z2,
                                                const int* __restrict__ labels,
                                                float* __restrict__ out, int n) {
    __shared__ int    h[C];
    __shared__ int    basec[C];
    __shared__ int    scan[128];
    __shared__ float4 zi[4][D4];
    __shared__ float  red[NT];
    __shared__ float  sl[C2];

    int t = threadIdx.x, bid = blockIdx.x;
    int n4 = n >> 2;
    const int4* l4 = (const int4*)labels;

    // ============ phase 0: per-block histogram partials ============
    if (t < C) h[t] = 0;
    __syncthreads();
    for (int i = bid * NT + t; i < n4; i += NB * NT) {
        int4 v = l4[i];
        atomicAdd(&h[v.x], 1); atomicAdd(&h[v.y], 1);
        atomicAdd(&h[v.z], 1); atomicAdd(&h[v.w], 1);
    }
    if (bid == 0 && t < (n & 3)) atomicAdd(&h[labels[(n4 << 2) + t]], 1);
    __syncthreads();
    if (t < C) g_hist_part[bid][t] = h[t];
    grid_barrier(0);

    // ============ phase 1: scan + scatter ============
    bool active = (bid * NT) < n4 || bid == 0;
    if (active) {
        int tot = 0, pre = 0;
        if (t < C) {
            for (int bb = 0; bb < NB; bb++) {
                int v = g_hist_part[bb][t];
                tot += v;
                if (bb < bid) pre += v;
            }
            h[t] = 0;
        }
        if (t < 128) scan[t] = (t < C) ? tot : 0;
        __syncthreads();
        for (int o = 1; o < 128; o <<= 1) {
            int v = 0;
            if (t < 128) { v = scan[t]; if (t >= o) v += scan[t - o]; }
            __syncthreads();
            if (t < 128) scan[t] = v;
            __syncthreads();
        }
        if (t < C) {
            basec[t] = (scan[t] - tot) + pre;
            if (bid == 0) {
                g_counts[t]  = tot;
                g_offsets[t] = scan[t] - tot;
                if (t == C - 1) g_offsets[C] = scan[t];
            }
        }
        __syncthreads();
        for (int i = bid * NT + t; i < n4; i += NB * NT) {
            int4 v = l4[i];
            int i0 = i * 4;
            int r0 = atomicAdd(&h[v.x], 1);
            int r1 = atomicAdd(&h[v.y], 1);
            int r2 = atomicAdd(&h[v.z], 1);
            int r3 = atomicAdd(&h[v.w], 1);
            g_perm[basec[v.x] + r0] = i0;
            g_perm[basec[v.y] + r1] = i0 + 1;
            g_perm[basec[v.z] + r2] = i0 + 2;
            g_perm[basec[v.w] + r3] = i0 + 3;
        }
        if (bid == 0) {
            __syncthreads();
            if (t < (n & 3)) {
                int lab = labels[(n4 << 2) + t];
                int r = atomicAdd(&h[lab], 1);
                g_perm[basec[lab] + r] = (n4 << 2) + t;
            }
        }
    }
    grid_barrier(1);

    // ============ phase 2: segment sum (grid-stride over units) ============
    {
        const float4* z1v = (const float4*)z1;
        const float4* z2v = (const float4*)z2;
        for (int unit = bid; unit < C * CHUNKS; unit += NB) {
            int c = unit / CHUNKS, ch = unit % CHUNKS;
            int s = g_offsets[c], e = g_offsets[c + 1];
            int cnt = e - s;
            int per = (cnt + CHUNKS - 1) / CHUNKS;
            int r0 = s + ch * per;
            int r1 = min(r0 + per, e);

            float4 a1 = make_float4(0.f, 0.f, 0.f, 0.f);
            float4 a2 = make_float4(0.f, 0.f, 0.f, 0.f);
            int j = r0;
            for (; j + 4 <= r1; j += 4) {
                int p0 = g_perm[j], p1 = g_perm[j + 1], p2 = g_perm[j + 2], p3 = g_perm[j + 3];
                float4 u0 = z1v[p0 * D4 + t], u1 = z1v[p1 * D4 + t];
                float4 u2 = z1v[p2 * D4 + t], u3 = z1v[p3 * D4 + t];
                float4 w0 = z2v[p0 * D4 + t], w1 = z2v[p1 * D4 + t];
                float4 w2 = z2v[p2 * D4 + t], w3 = z2v[p3 * D4 + t];
                a1.x += (u0.x + u1.x) + (u2.x + u3.x);
                a1.y += (u0.y + u1.y) + (u2.y + u3.y);
                a1.z += (u0.z + u1.z) + (u2.z + u3.z);
                a1.w += (u0.w + u1.w) + (u2.w + u3.w);
                a2.x += (w0.x + w1.x) + (w2.x + w3.x);
                a2.y += (w0.y + w1.y) + (w2.y + w3.y);
                a2.z += (w0.z + w1.z) + (w2.z + w3.z);
                a2.w += (w0.w + w1.w) + (w2.w + w3.w);
            }
            for (; j < r1; j++) {
                int p = g_perm[j];
                float4 u = z1v[p * D4 + t], w = z2v[p * D4 + t];
                a1.x += u.x; a1.y += u.y; a1.z += u.z; a1.w += u.w;
                a2.x += w.x; a2.y += w.y; a2.z += w.z; a2.w += w.w;
            }
            g_part[0][c][ch][t] = a1;
            g_part[1][c][ch][t] = a2;
        }
    }
    grid_barrier(2);

    // ============ phase 3: prototypes + l2 normalize ============
    if (bid < C2) {
        int row = bid;
        int half = row / C, c = row - half * C;
        float4 p = make_float4(0.f, 0.f, 0.f, 0.f);
#pragma unroll
        for (int ch = 0; ch < CHUNKS; ch++) {
            float4 q = g_part[half][c][ch][t];
            p.x += q.x; p.y += q.y; p.z += q.z; p.w += q.w;
        }
        float inv_d = 1.0f / fmaxf((float)g_counts[c], 1.0f);
        p.x *= inv_d; p.y *= inv_d; p.z *= inv_d; p.w *= inv_d;

        float* o = out + 1 + row * D + t * 4;
        o[0] = p.x; o[1] = p.y; o[2] = p.z; o[3] = p.w;

        red[t] = p.x * p.x + p.y * p.y + p.z * p.z + p.w * p.w;
        __syncthreads();
        if (t < 64) red[t] += red[t + 64] + red[t + 128];
        __syncthreads();
        for (int o2 = 32; o2 > 0; o2 >>= 1) {
            if (t < o2) red[t] += red[t + o2];
            __syncthreads();
        }
        float inv = 1.0f / fmaxf(sqrtf(red[0]), EPS_N);
        float4 zn = make_float4(p.x * inv, p.y * inv, p.z * inv, p.w * inv);
        g_z4[row * D4 + t] = zn;
        int col = t * 4;
        g_zT[col * C2 + row]       = zn.x;
        g_zT[(col + 1) * C2 + row] = zn.y;
        g_zT[(col + 2) * C2 + row] = zn.z;
        g_zT[(col + 3) * C2 + row] = zn.w;
    }
    grid_barrier(3);

    // ============ phase 4: Gram rows + masked softmax ============
    if (bid < C2 / 4) {
        int ib = bid * 4;
#pragma unroll
        for (int q = 0; q < 4; q++) zi[q][t] = g_z4[(ib + q) * D4 + t];
        __syncthreads();

        bool ex = t < 8;            // this thread also owns column 192+t
        int c1 = t, cx = 192 + t;
        bool v1 = g_counts[c1 % C] > 0;
        bool vx = ex && (g_counts[cx % C] > 0);

        float d0 = 0.f, d1 = 0.f, d2 = 0.f, d3 = 0.f;
        float x0 = 0.f, x1 = 0.f, x2 = 0.f, x3 = 0.f;
#pragma unroll 4
        for (int k4 = 0; k4 < D4; k4++) {
            float4 v0q = zi[0][k4], v1q = zi[1][k4], v2q = zi[2][k4], v3q = zi[3][k4];
            const float* zT = &g_zT[(k4 * 4) * C2];
            float b0 = zT[t], b1 = zT[C2 + t], b2 = zT[2 * C2 + t], b3 = zT[3 * C2 + t];
            d0 = fmaf(v0q.x, b0, d0); d0 = fmaf(v0q.y, b1, d0);
            d0 = fmaf(v0q.z, b2, d0); d0 = fmaf(v0q.w, b3, d0);
            d1 = fmaf(v1q.x, b0, d1); d1 = fmaf(v1q.y, b1, d1);
            d1 = fmaf(v1q.z, b2, d1); d1 = fmaf(v1q.w, b3, d1);
            d2 = fmaf(v2q.x, b0, d2); d2 = fmaf(v2q.y, b1, d2);
            d2 = fmaf(v2q.z, b2, d2); d2 = fmaf(v2q.w, b3, d2);
            d3 = fmaf(v3q.x, b0, d3); d3 = fmaf(v3q.y, b1, d3);
            d3 = fmaf(v3q.z, b2, d3); d3 = fmaf(v3q.w, b3, d3);
            if (ex) {
                float e0 = zT[cx], e1 = zT[C2 + cx], e2 = zT[2 * C2 + cx], e3 = zT[3 * C2 + cx];
                x0 = fmaf(v0q.x, e0, x0); x0 = fmaf(v0q.y, e1, x0);
                x0 = fmaf(v0q.z, e2, x0); x0 = fmaf(v0q.w, e3, x0);
                x1 = fmaf(v1q.x, e0, x1); x1 = fmaf(v1q.y, e1, x1);
                x1 = fmaf(v1q.z, e2, x1); x1 = fmaf(v1q.w, e3, x1);
                x2 = fmaf(v2q.x, e0, x2); x2 = fmaf(v2q.y, e1, x2);
                x2 = fmaf(v2q.z, e2, x2); x2 = fmaf(v2q.w, e3, x2);
                x3 = fmaf(v3q.x, e0, x3); x3 = fmaf(v3q.y, e1, x3);
                x3 = fmaf(v3q.z, e2, x3); x3 = fmaf(v3q.w, e3, x3);
            }
        }
        float dq[4] = {d0, d1, d2, d3};
        float xq[4] = {x0, x1, x2, x3};

#pragma unroll
        for (int q = 0; q < 4; q++) {
            int i = ib + q;
            float l1 = dq[q] * INV_T;
            float lx = xq[q] * INV_T;
            float m_own = v1 ? l1 : -FLT_MAX;
            if (vx) m_own = fmaxf(m_own, lx);
            red[t] = m_own;
            __syncthreads();
            if (t < 64) red[t] = fmaxf(red[t], fmaxf(red[t + 64], red[t + 128]));
            __syncthreads();
            for (int o2 = 32; o2 > 0; o2 >>= 1) {
                if (t < o2) red[t] = fmaxf(red[t], red[t + o2]);
                __syncthreads();
            }
            float m = red[0];
            __syncthreads();
            float e = (v1 && c1 != i) ? expf(l1 - m) : 0.f;
            if (vx && cx != i) e += expf(lx - m);
            sl[c1] = l1;
            if (ex) sl[cx] = lx;
            red[t] = e;
            __syncthreads();
            if (t < 64) red[t] += red[t + 64] + red[t + 128];
            __syncthreads();
            for (int o2 = 32; o2 > 0; o2 >>= 1) {
                if (t < o2) red[t] += red[t + o2];
                __syncthreads();
            }
            float S = red[0];
            if (t == 0) {
                int pos = (i + C) % C2;
                bool vi = g_counts[i % C] > 0;   // pos%C == i%C -> same validity
                g_rowloss[i] = vi ? (sl[pos] - m - logf(S)) : 0.f;
            }
            __syncthreads();
        }
    }
    grid_barrier(4);

    // ============ phase 5: final loss ============
    if (bid == 0) {
        float v = g_rowloss[t];
        if (t < 8) v += g_rowloss[192 + t];
        red[t] = v;
        __syncthreads();
        if (t < 64) red[t] += red[t + 64] + red[t + 128];
        __syncthreads();
        for (int o2 = 32; o2 > 0; o2 >>= 1) {
            if (t < o2) red[t] += red[t + o2];
            __syncthreads();
        }
        float tot = red[0];
        __syncthreads();
        red[t] = (t < C && g_counts[t] > 0) ? 2.f : 0.f;
        __syncthreads();
        if (t < 64) red[t] += red[t + 64] + red[t + 128];
        __syncthreads();
        for (int o2 = 32; o2 > 0; o2 >>= 1) {
            if (t < o2) red[t] += red[t + o2];
            __syncthreads();
        }
        if (t == 0) out[0] = -tot / fmaxf(red[0], 1.f);
    }
}

// ---------------------------------------------------------------- launch
extern "C" void kernel_launch(void* const* d_in, const int* in_sizes, int n_in,
                              void* d_out, int out_size) {
    const float* z1     = (const float*)d_in[0];
    const float* z2     = (const float*)d_in[1];
    const int*   labels = (const int*)d_in[2];
    float*       out    = (float*)d_out;
    int n = in_sizes[2];   // 32768

    k_reset<<<1, 32>>>();
    k_mega<<<NB, NT>>>(z1, z2, labels, out, n);
}